// round 2
// baseline (speedup 1.0000x reference)
#include <cuda_runtime.h>
#include <cstddef>

#define BB 64
#define PP 2000
#define DD 128
#define TT 200
#define EPSL 1e-5f

// ---------------- scratch (static device arrays; no allocation) ----------------
__device__ float g_tour [BB * TT * DD];   // segment sums        (6.55 MB)
__device__ float g_tb   [BB * TT * DD];   // tour_emb @ W1b + b1 (6.55 MB)
__device__ float g_added[BB * PP * DD];   // residual output     (65.5 MB)
__device__ float g_sum  [BB * DD];
__device__ float g_sumsq[BB * DD];

// ---------------- K0: zero accumulators ----------------
__global__ void k_zero() {
    int i = blockIdx.x * blockDim.x + threadIdx.x;
    if (i < BB * TT * DD) g_tour[i] = 0.f;
    if (i < BB * DD) { g_sum[i] = 0.f; g_sumsq[i] = 0.f; }
}

// ---------------- K1: segment sum via vector atomics ----------------
__global__ void k_seg(const float* __restrict__ emb, const int* __restrict__ tidx) {
    int i = blockIdx.x * blockDim.x + threadIdx.x;   // (row, d4) pairs
    int d4 = i & 31;
    int r  = i >> 5;
    if (r >= BB * PP) return;
    int b = r / PP, p = r - b * PP;
    const float4 v = *reinterpret_cast<const float4*>(emb + (size_t)(b * 2001 + 1 + p) * DD + d4 * 4);
    int t = tidx[r];
    float4* dst = reinterpret_cast<float4*>(g_tour + (size_t)(b * TT + t) * DD + d4 * 4);
    atomicAdd(dst, v);   // red.global.v4 (sm_90+)
}

// ---------------- K2: tb = tour_emb @ W1b + b1  (12800 x 128, K=128) ----------------
// CTA: 64 rows x 128 cols, 256 threads (16x16), K-chunks of 32
__global__ void k_tb(const float* __restrict__ W1, const float* __restrict__ b1) {
    extern __shared__ float smem[];
    float* As = smem;            // 64 * 132
    float* Ws = smem + 64 * 132; // 32 * 128
    int tid = threadIdx.x;
    int tx = tid & 15, ty = tid >> 4;
    int row0 = blockIdx.x * 64;

    // load A tile (64 x 128)
    for (int i = tid; i < 64 * 32; i += 256) {
        int r = i >> 5, c4 = i & 31;
        float4 v = *reinterpret_cast<const float4*>(g_tour + (size_t)(row0 + r) * DD + c4 * 4);
        *reinterpret_cast<float4*>(As + r * 132 + c4 * 4) = v;
    }

    float acc[4][8];
#pragma unroll
    for (int i = 0; i < 4; i++)
#pragma unroll
        for (int j = 0; j < 8; j++) acc[i][j] = 0.f;

    const float* Wb = W1 + 128 * DD;  // W1 rows [128:256)
    for (int kc = 0; kc < 128; kc += 32) {
        __syncthreads();
        for (int i = tid; i < 32 * 32; i += 256) {
            int r = i >> 5, c4 = i & 31;
            *reinterpret_cast<float4*>(Ws + r * 128 + c4 * 4) =
                *reinterpret_cast<const float4*>(Wb + (size_t)(kc + r) * DD + c4 * 4);
        }
        __syncthreads();
#pragma unroll
        for (int k = 0; k < 32; k++) {
            float a[4];
#pragma unroll
            for (int i = 0; i < 4; i++) a[i] = As[(ty * 4 + i) * 132 + kc + k];
            float4 w0 = *reinterpret_cast<const float4*>(Ws + k * 128 + tx * 8);
            float4 w1 = *reinterpret_cast<const float4*>(Ws + k * 128 + tx * 8 + 4);
            float w[8] = {w0.x, w0.y, w0.z, w0.w, w1.x, w1.y, w1.z, w1.w};
#pragma unroll
            for (int i = 0; i < 4; i++)
#pragma unroll
                for (int j = 0; j < 8; j++) acc[i][j] += a[i] * w[j];
        }
    }

    float4 bv0 = *reinterpret_cast<const float4*>(b1 + tx * 8);
    float4 bv1 = *reinterpret_cast<const float4*>(b1 + tx * 8 + 4);
    float bb[8] = {bv0.x, bv0.y, bv0.z, bv0.w, bv1.x, bv1.y, bv1.z, bv1.w};
#pragma unroll
    for (int i = 0; i < 4; i++) {
        int r = row0 + ty * 4 + i;
        float* dst = g_tb + (size_t)r * DD + tx * 8;
#pragma unroll
        for (int j = 0; j < 8; j++) dst[j] = acc[i][j] + bb[j];
    }
}

// ---------------- K3: fused MLP + residual + stat accumulation ----------------
// grid = (32 tiles, 64 batches); CTA: 64 rows x 128 cols, 256 threads
__global__ void k_main(const float* __restrict__ emb, const int* __restrict__ tidx,
                       const float* __restrict__ W1, const float* __restrict__ W2,
                       const float* __restrict__ b2) {
    extern __shared__ float smem[];
    float* As = smem;              // 64 * 132
    float* Hs = smem + 8448;       // 64 * 132
    float* Ws = smem + 16896;      // 32 * 128 (also reduction scratch, 4096 f)
    int*   ts = (int*)(smem + 20992); // 64

    int tid = threadIdx.x;
    int tx = tid & 15, ty = tid >> 4;
    int b = blockIdx.y;
    int row0 = blockIdx.x * 64;
    int nrows = PP - row0; if (nrows > 64) nrows = 64;

    // load A tile = cust rows (zero-pad invalid rows)
    for (int i = tid; i < 64 * 32; i += 256) {
        int r = i >> 5, c4 = i & 31;
        float4 v = make_float4(0.f, 0.f, 0.f, 0.f);
        if (r < nrows)
            v = *reinterpret_cast<const float4*>(emb + (size_t)(b * 2001 + 1 + row0 + r) * DD + c4 * 4);
        *reinterpret_cast<float4*>(As + r * 132 + c4 * 4) = v;
    }
    if (tid < 64) {
        int t = 0;
        if (tid < nrows) t = tidx[b * PP + row0 + tid];
        ts[tid] = t;
    }

    float acc[4][8];
#pragma unroll
    for (int i = 0; i < 4; i++)
#pragma unroll
        for (int j = 0; j < 8; j++) acc[i][j] = 0.f;

    // ---- phase 1: acc = A @ W1a ----
    for (int kc = 0; kc < 128; kc += 32) {
        __syncthreads();
        for (int i = tid; i < 32 * 32; i += 256) {
            int r = i >> 5, c4 = i & 31;
            *reinterpret_cast<float4*>(Ws + r * 128 + c4 * 4) =
                *reinterpret_cast<const float4*>(W1 + (size_t)(kc + r) * DD + c4 * 4);
        }
        __syncthreads();
#pragma unroll
        for (int k = 0; k < 32; k++) {
            float a[4];
#pragma unroll
            for (int i = 0; i < 4; i++) a[i] = As[(ty * 4 + i) * 132 + kc + k];
            float4 w0 = *reinterpret_cast<const float4*>(Ws + k * 128 + tx * 8);
            float4 w1 = *reinterpret_cast<const float4*>(Ws + k * 128 + tx * 8 + 4);
            float w[8] = {w0.x, w0.y, w0.z, w0.w, w1.x, w1.y, w1.z, w1.w};
#pragma unroll
            for (int i = 0; i < 4; i++)
#pragma unroll
                for (int j = 0; j < 8; j++) acc[i][j] += a[i] * w[j];
        }
    }

    // tb gather + relu -> Hs
#pragma unroll
    for (int i = 0; i < 4; i++) {
        int t = ts[ty * 4 + i];
        const float* tbp = g_tb + (size_t)(b * TT + t) * DD + tx * 8;
        float4 t0 = *reinterpret_cast<const float4*>(tbp);
        float4 t1 = *reinterpret_cast<const float4*>(tbp + 4);
        float tv[8] = {t0.x, t0.y, t0.z, t0.w, t1.x, t1.y, t1.z, t1.w};
        float* hrow = Hs + (ty * 4 + i) * 132 + tx * 8;
#pragma unroll
        for (int j = 0; j < 8; j++) {
            float h = acc[i][j] + tv[j];
            hrow[j] = fmaxf(h, 0.f);
            acc[i][j] = 0.f;   // reuse as phase-2 accumulator
        }
    }
    __syncthreads();

    // ---- phase 2: acc = H @ W2 ----
    for (int kc = 0; kc < 128; kc += 32) {
        for (int i = tid; i < 32 * 32; i += 256) {
            int r = i >> 5, c4 = i & 31;
            *reinterpret_cast<float4*>(Ws + r * 128 + c4 * 4) =
                *reinterpret_cast<const float4*>(W2 + (size_t)(kc + r) * DD + c4 * 4);
        }
        __syncthreads();
#pragma unroll
        for (int k = 0; k < 32; k++) {
            float a[4];
#pragma unroll
            for (int i = 0; i < 4; i++) a[i] = Hs[(ty * 4 + i) * 132 + kc + k];
            float4 w0 = *reinterpret_cast<const float4*>(Ws + k * 128 + tx * 8);
            float4 w1 = *reinterpret_cast<const float4*>(Ws + k * 128 + tx * 8 + 4);
            float w[8] = {w0.x, w0.y, w0.z, w0.w, w1.x, w1.y, w1.z, w1.w};
#pragma unroll
            for (int i = 0; i < 4; i++)
#pragma unroll
                for (int j = 0; j < 8; j++) acc[i][j] += a[i] * w[j];
        }
        __syncthreads();
    }

    // ---- epilogue: added = acc + b2 + cust; write gmem + in-place As ----
    float4 bv0 = *reinterpret_cast<const float4*>(b2 + tx * 8);
    float4 bv1 = *reinterpret_cast<const float4*>(b2 + tx * 8 + 4);
    float bb2[8] = {bv0.x, bv0.y, bv0.z, bv0.w, bv1.x, bv1.y, bv1.z, bv1.w};
#pragma unroll
    for (int i = 0; i < 4; i++) {
        int r = ty * 4 + i;
        if (r < nrows) {
            float* arow = As + r * 132 + tx * 8;
            float* drow = g_added + (size_t)(b * PP + row0 + r) * DD + tx * 8;
#pragma unroll
            for (int j = 0; j < 8; j++) {
                float v = acc[i][j] + bb2[j] + arow[j];
                arow[j] = v;
                drow[j] = v;
            }
        }
    }
    __syncthreads();

    // ---- per-column sum / sumsq reduction over valid rows ----
    int col = tid & 127, half = tid >> 7;
    float s = 0.f, ss = 0.f;
    for (int r = half; r < nrows; r += 2) {
        float v = As[r * 132 + col];
        s += v; ss += v * v;
    }
    Ws[half * 128 + col]       = s;
    Ws[256 + half * 128 + col] = ss;
    __syncthreads();
    if (tid < 128) {
        float st  = Ws[tid] + Ws[128 + tid];
        float sst = Ws[256 + tid] + Ws[384 + tid];
        atomicAdd(&g_sum[b * DD + tid], st);
        atomicAdd(&g_sumsq[b * DD + tid], sst);
    }
}

// ---------------- K4: convert sums to (scale, shift) ----------------
__global__ void k_stat(const float* __restrict__ gamma, const float* __restrict__ beta) {
    int i = blockIdx.x * blockDim.x + threadIdx.x;
    if (i >= BB * DD) return;
    int d = i & 127;
    float mean = g_sum[i] * (1.f / PP);
    float var  = g_sumsq[i] * (1.f / PP) - mean * mean;
    float sc = gamma[d] * rsqrtf(var + EPSL);
    float sh = beta[d] - mean * sc;
    g_sum[i] = sc;
    g_sumsq[i] = sh;
}

// ---------------- K5: normalize + depot-row copy ----------------
__global__ void k_norm(const float* __restrict__ emb, float* __restrict__ out) {
    int i = blockIdx.x * blockDim.x + threadIdx.x;   // float4 index
    const int N4 = BB * 2001 * 32;
    if (i >= N4) return;
    int d4 = i & 31;
    int row = i >> 5;
    int b = row / 2001;
    int pr = row - b * 2001;
    float4 o;
    if (pr == 0) {
        o = reinterpret_cast<const float4*>(emb)[i];
    } else {
        int p = pr - 1;
        float4 a = *reinterpret_cast<const float4*>(g_added + (size_t)(b * PP + p) * DD + d4 * 4);
        float4 s4 = *reinterpret_cast<const float4*>(g_sum + b * DD + d4 * 4);
        float4 h4 = *reinterpret_cast<const float4*>(g_sumsq + b * DD + d4 * 4);
        o.x = a.x * s4.x + h4.x;
        o.y = a.y * s4.y + h4.y;
        o.z = a.z * s4.z + h4.z;
        o.w = a.w * s4.w + h4.w;
    }
    reinterpret_cast<float4*>(out)[i] = o;
}

// ---------------- launch ----------------
extern "C" void kernel_launch(void* const* d_in, const int* in_sizes, int n_in,
                              void* d_out, int out_size) {
    // locate tour_index (the unique input of size B*P = 128000); rest follow in dict order
    int ti = -1;
    for (int i = 0; i < n_in; i++) {
        if (in_sizes[i] == BB * PP) { ti = i; break; }
    }
    const int*   tidx  = (const int*)  d_in[ti];
    const float* emb   = (const float*)d_in[ti + 1];
    const float* W1    = (const float*)d_in[ti + 2];
    const float* b1    = (const float*)d_in[ti + 3];
    const float* W2    = (const float*)d_in[ti + 4];
    const float* b2    = (const float*)d_in[ti + 5];
    const float* gamma = (const float*)d_in[ti + 6];
    const float* beta  = (const float*)d_in[ti + 7];
    float* out = (float*)d_out;

    const int SMEM_TB   = (64 * 132 + 32 * 128) * 4;                // 50176
    const int SMEM_MAIN = (64 * 132 * 2 + 32 * 128) * 4 + 64 * 4;   // 84480
    cudaFuncSetAttribute(k_tb,   cudaFuncAttributeMaxDynamicSharedMemorySize, SMEM_TB);
    cudaFuncSetAttribute(k_main, cudaFuncAttributeMaxDynamicSharedMemorySize, SMEM_MAIN);

    k_zero<<<(BB * TT * DD + 255) / 256, 256>>>();
    k_seg<<<(BB * PP * 32 + 255) / 256, 256>>>(emb, tidx);
    k_tb<<<(BB * TT) / 64, 256, SMEM_TB>>>(W1, b1);
    k_main<<<dim3((PP + 63) / 64, BB), 256, SMEM_MAIN>>>(emb, tidx, W1, W2, b2);
    k_stat<<<(BB * DD + 255) / 256, 256>>>(gamma, beta);
    k_norm<<<(BB * 2001 * 32 + 255) / 256, 256>>>(emb, out);
}

// round 3
// speedup vs baseline: 2.1436x; 2.1436x over previous
#include <cuda_runtime.h>
#include <cuda_bf16.h>
#include <cstddef>

#define BB 64
#define PP 2000
#define DD 128
#define TT 200
#define EPSL 1e-5f

// ---------------- scratch ----------------
__device__ float g_tour [BB * TT * DD];
__device__ float g_tb   [BB * TT * DD];
__device__ float g_added[BB * PP * DD];
__device__ float g_sum  [BB * DD];
__device__ float g_sumsq[BB * DD];
// packed bf16x2 weights: [n][kp] kp in [0,64), pair = (W[2kp][n], W[2kp+1][n])
__device__ unsigned g_W1h[DD * 64];
__device__ unsigned g_W1l[DD * 64];
__device__ unsigned g_W2h[DD * 64];
__device__ unsigned g_W2l[DD * 64];

static __device__ __forceinline__ unsigned b2u(__nv_bfloat162 h) {
    return *reinterpret_cast<unsigned*>(&h);
}
static __device__ __forceinline__ __nv_bfloat162 u2b(unsigned u) {
    return *reinterpret_cast<__nv_bfloat162*>(&u);
}
// pack (v0 -> low, v1 -> high) hi part; also produce lo residual pack
static __device__ __forceinline__ void split_pack(float v0, float v1,
                                                  unsigned& hi, unsigned& lo) {
    __nv_bfloat162 h = __floats2bfloat162_rn(v0, v1);
    float r0 = v0 - __bfloat162float(h.x);
    float r1 = v1 - __bfloat162float(h.y);
    __nv_bfloat162 l = __floats2bfloat162_rn(r0, r1);
    hi = b2u(h); lo = b2u(l);
}

static __device__ __forceinline__ void mma16816(float* c, unsigned a0, unsigned a1,
                                                unsigned a2, unsigned a3,
                                                unsigned b0, unsigned b1) {
    asm volatile(
        "mma.sync.aligned.m16n8k16.row.col.f32.bf16.bf16.f32 "
        "{%0,%1,%2,%3}, {%4,%5,%6,%7}, {%8,%9}, {%0,%1,%2,%3};"
        : "+f"(c[0]), "+f"(c[1]), "+f"(c[2]), "+f"(c[3])
        : "r"(a0), "r"(a1), "r"(a2), "r"(a3), "r"(b0), "r"(b1));
}

// ---------------- K0: zero ----------------
__global__ void k_zero() {
    int i = blockIdx.x * blockDim.x + threadIdx.x;
    if (i < BB * TT * DD) g_tour[i] = 0.f;
    if (i < BB * DD) { g_sum[i] = 0.f; g_sumsq[i] = 0.f; }
}

// ---------------- K pack: split W1a, W2 into bf16 hi/lo ----------------
__global__ void k_pack(const float* __restrict__ W1, const float* __restrict__ W2) {
    int i = blockIdx.x * blockDim.x + threadIdx.x;   // 2 * 128 * 64
    if (i >= 2 * DD * 64) return;
    int m  = i >> 13;
    int n  = (i >> 6) & 127;
    int kp = i & 63;
    const float* W = (m == 0) ? W1 : W2;
    float v0 = W[(2 * kp    ) * DD + n];
    float v1 = W[(2 * kp + 1) * DD + n];
    unsigned hi, lo;
    split_pack(v0, v1, hi, lo);
    if (m == 0) { g_W1h[n * 64 + kp] = hi; g_W1l[n * 64 + kp] = lo; }
    else        { g_W2h[n * 64 + kp] = hi; g_W2l[n * 64 + kp] = lo; }
}

// ---------------- K1: segment sum ----------------
__global__ void k_seg(const float* __restrict__ emb, const int* __restrict__ tidx) {
    int i = blockIdx.x * blockDim.x + threadIdx.x;
    int d4 = i & 31;
    int r  = i >> 5;
    if (r >= BB * PP) return;
    int b = r / PP, p = r - b * PP;
    const float4 v = *reinterpret_cast<const float4*>(emb + (size_t)(b * 2001 + 1 + p) * DD + d4 * 4);
    int t = tidx[r];
    float4* dst = reinterpret_cast<float4*>(g_tour + (size_t)(b * TT + t) * DD + d4 * 4);
    atomicAdd(dst, v);
}

// ---------------- K2: tb = tour_emb @ W1b + b1 (FFMA; small) ----------------
__global__ void k_tb(const float* __restrict__ W1, const float* __restrict__ b1) {
    extern __shared__ float smem[];
    float* As = smem;
    float* Ws = smem + 64 * 132;
    int tid = threadIdx.x;
    int tx = tid & 15, ty = tid >> 4;
    int row0 = blockIdx.x * 64;

    for (int i = tid; i < 64 * 32; i += 256) {
        int r = i >> 5, c4 = i & 31;
        float4 v = *reinterpret_cast<const float4*>(g_tour + (size_t)(row0 + r) * DD + c4 * 4);
        *reinterpret_cast<float4*>(As + r * 132 + c4 * 4) = v;
    }
    float acc[4][8];
#pragma unroll
    for (int i = 0; i < 4; i++)
#pragma unroll
        for (int j = 0; j < 8; j++) acc[i][j] = 0.f;

    const float* Wb = W1 + 128 * DD;
    for (int kc = 0; kc < 128; kc += 32) {
        __syncthreads();
        for (int i = tid; i < 32 * 32; i += 256) {
            int r = i >> 5, c4 = i & 31;
            *reinterpret_cast<float4*>(Ws + r * 128 + c4 * 4) =
                *reinterpret_cast<const float4*>(Wb + (size_t)(kc + r) * DD + c4 * 4);
        }
        __syncthreads();
#pragma unroll
        for (int k = 0; k < 32; k++) {
            float a[4];
#pragma unroll
            for (int i = 0; i < 4; i++) a[i] = As[(ty * 4 + i) * 132 + kc + k];
            float4 w0 = *reinterpret_cast<const float4*>(Ws + k * 128 + tx * 8);
            float4 w1 = *reinterpret_cast<const float4*>(Ws + k * 128 + tx * 8 + 4);
            float w[8] = {w0.x, w0.y, w0.z, w0.w, w1.x, w1.y, w1.z, w1.w};
#pragma unroll
            for (int i = 0; i < 4; i++)
#pragma unroll
                for (int j = 0; j < 8; j++) acc[i][j] += a[i] * w[j];
        }
    }
    float4 bv0 = *reinterpret_cast<const float4*>(b1 + tx * 8);
    float4 bv1 = *reinterpret_cast<const float4*>(b1 + tx * 8 + 4);
    float bb[8] = {bv0.x, bv0.y, bv0.z, bv0.w, bv1.x, bv1.y, bv1.z, bv1.w};
#pragma unroll
    for (int i = 0; i < 4; i++) {
        int r = row0 + ty * 4 + i;
        float* dst = g_tb + (size_t)r * DD + tx * 8;
#pragma unroll
        for (int j = 0; j < 8; j++) dst[j] = acc[i][j] + bb[j];
    }
}

// ---------------- K3: fused MLP via mma.sync bf16 split ----------------
// smem (u32 units):
//   Ah[64*68], Al[64*68], Hh[64*68], Hl[64*68], Wh[128*36], Wl[128*36], ts[64]
// After phase2 MMAs, Hh..Hl region reused as f32 added-tile [64][132],
// Wh region reused as f32 reduction scratch[512].
#define SA 68
#define SW 36
#define OFF_AH 0
#define OFF_AL (64 * SA)
#define OFF_HH (2 * 64 * SA)
#define OFF_HL (3 * 64 * SA)
#define OFF_WH (4 * 64 * SA)
#define OFF_WL (4 * 64 * SA + 128 * SW)
#define OFF_TS (4 * 64 * SA + 2 * 128 * SW)
#define SMEM_U32 (OFF_TS + 64)

__global__ void __launch_bounds__(256, 2)
k_main(const float* __restrict__ emb, const int* __restrict__ tidx,
       const float* __restrict__ b2) {
    extern __shared__ unsigned su[];
    unsigned* Ah = su + OFF_AH;
    unsigned* Al = su + OFF_AL;
    unsigned* Hh = su + OFF_HH;
    unsigned* Hl = su + OFF_HL;
    unsigned* Wh = su + OFF_WH;
    unsigned* Wl = su + OFF_WL;
    int* ts = (int*)(su + OFF_TS);
    float* Ad   = (float*)(su + OFF_HH);  // [64][132] after phase2
    float* redc = (float*)(su + OFF_WH);  // [512] after phase2

    int tid = threadIdx.x;
    int lane = tid & 31, wid = tid >> 5;
    int g = lane >> 2, t4 = lane & 3;
    int wr = wid & 3, wc = wid >> 2;
    int b = blockIdx.y;
    int row0 = blockIdx.x * 64;
    int nrows = PP - row0; if (nrows > 64) nrows = 64;

    // ---- load + split-pack A tile ----
    for (int i = tid; i < 64 * 32; i += 256) {
        int r = i >> 5, c4 = i & 31;
        float4 v = make_float4(0.f, 0.f, 0.f, 0.f);
        if (r < nrows)
            v = *reinterpret_cast<const float4*>(emb + (size_t)(b * 2001 + 1 + row0 + r) * DD + c4 * 4);
        unsigned h0, l0, h1, l1;
        split_pack(v.x, v.y, h0, l0);
        split_pack(v.z, v.w, h1, l1);
        Ah[r * SA + 2 * c4]     = h0;  Al[r * SA + 2 * c4]     = l0;
        Ah[r * SA + 2 * c4 + 1] = h1;  Al[r * SA + 2 * c4 + 1] = l1;
    }
    if (tid < 64) {
        int t = 0;
        if (tid < nrows) t = tidx[b * PP + row0 + tid];
        ts[tid] = t;
    }

    float acc[8][4];
#pragma unroll
    for (int j = 0; j < 8; j++)
#pragma unroll
        for (int i = 0; i < 4; i++) acc[j][i] = 0.f;

    int r0 = wr * 16 + g;      // this thread's two output rows
    int r1 = r0 + 8;

    // ================= phase 1: acc = A @ W1a =================
    for (int c = 0; c < 2; c++) {
        __syncthreads();
        for (int i = tid; i < 1024; i += 256) {        // copy W chunk (uint4)
            int n = i >> 3, k4 = (i & 7) * 4;
            *reinterpret_cast<uint4*>(Wh + n * SW + k4) =
                *reinterpret_cast<const uint4*>(g_W1h + n * 64 + c * 32 + k4);
            *reinterpret_cast<uint4*>(Wl + n * SW + k4) =
                *reinterpret_cast<const uint4*>(g_W1l + n * 64 + c * 32 + k4);
        }
        __syncthreads();
#pragma unroll
        for (int s = 0; s < 4; s++) {
            int base = c * 32 + s * 8;
            unsigned a0h = Ah[r0 * SA + base + t4],     a0l = Al[r0 * SA + base + t4];
            unsigned a1h = Ah[r1 * SA + base + t4],     a1l = Al[r1 * SA + base + t4];
            unsigned a2h = Ah[r0 * SA + base + t4 + 4], a2l = Al[r0 * SA + base + t4 + 4];
            unsigned a3h = Ah[r1 * SA + base + t4 + 4], a3l = Al[r1 * SA + base + t4 + 4];
#pragma unroll
            for (int jt = 0; jt < 8; jt++) {
                int n = wc * 64 + jt * 8 + g;
                unsigned b0h = Wh[n * SW + s * 8 + t4];
                unsigned b1h = Wh[n * SW + s * 8 + t4 + 4];
                unsigned b0l = Wl[n * SW + s * 8 + t4];
                unsigned b1l = Wl[n * SW + s * 8 + t4 + 4];
                mma16816(acc[jt], a0h, a1h, a2h, a3h, b0h, b1h);
                mma16816(acc[jt], a0l, a1l, a2l, a3l, b0h, b1h);
                mma16816(acc[jt], a0h, a1h, a2h, a3h, b0l, b1l);
            }
        }
    }

    // ---- tb gather + relu -> pack into H ----
    {
        const float* tb0p = g_tb + (size_t)(b * TT + ts[r0]) * DD;
        const float* tb1p = g_tb + (size_t)(b * TT + ts[r1]) * DD;
#pragma unroll
        for (int jt = 0; jt < 8; jt++) {
            int colb = wc * 64 + jt * 8 + 2 * t4;
            int cp   = wc * 32 + jt * 4 + t4;
            float2 tb0 = *reinterpret_cast<const float2*>(tb0p + colb);
            float2 tb1 = *reinterpret_cast<const float2*>(tb1p + colb);
            float h00 = fmaxf(acc[jt][0] + tb0.x, 0.f);
            float h01 = fmaxf(acc[jt][1] + tb0.y, 0.f);
            float h10 = fmaxf(acc[jt][2] + tb1.x, 0.f);
            float h11 = fmaxf(acc[jt][3] + tb1.y, 0.f);
            unsigned hh, hl;
            split_pack(h00, h01, hh, hl);
            Hh[r0 * SA + cp] = hh; Hl[r0 * SA + cp] = hl;
            split_pack(h10, h11, hh, hl);
            Hh[r1 * SA + cp] = hh; Hl[r1 * SA + cp] = hl;
#pragma unroll
            for (int i = 0; i < 4; i++) acc[jt][i] = 0.f;
        }
    }

    // ================= phase 2: acc = H @ W2 =================
    for (int c = 0; c < 2; c++) {
        __syncthreads();
        for (int i = tid; i < 1024; i += 256) {
            int n = i >> 3, k4 = (i & 7) * 4;
            *reinterpret_cast<uint4*>(Wh + n * SW + k4) =
                *reinterpret_cast<const uint4*>(g_W2h + n * 64 + c * 32 + k4);
            *reinterpret_cast<uint4*>(Wl + n * SW + k4) =
                *reinterpret_cast<const uint4*>(g_W2l + n * 64 + c * 32 + k4);
        }
        __syncthreads();
#pragma unroll
        for (int s = 0; s < 4; s++) {
            int base = c * 32 + s * 8;
            unsigned a0h = Hh[r0 * SA + base + t4],     a0l = Hl[r0 * SA + base + t4];
            unsigned a1h = Hh[r1 * SA + base + t4],     a1l = Hl[r1 * SA + base + t4];
            unsigned a2h = Hh[r0 * SA + base + t4 + 4], a2l = Hl[r0 * SA + base + t4 + 4];
            unsigned a3h = Hh[r1 * SA + base + t4 + 4], a3l = Hl[r1 * SA + base + t4 + 4];
#pragma unroll
            for (int jt = 0; jt < 8; jt++) {
                int n = wc * 64 + jt * 8 + g;
                unsigned b0h = Wh[n * SW + s * 8 + t4];
                unsigned b1h = Wh[n * SW + s * 8 + t4 + 4];
                unsigned b0l = Wl[n * SW + s * 8 + t4];
                unsigned b1l = Wl[n * SW + s * 8 + t4 + 4];
                mma16816(acc[jt], a0h, a1h, a2h, a3h, b0h, b1h);
                mma16816(acc[jt], a0l, a1l, a2l, a3l, b0h, b1h);
                mma16816(acc[jt], a0h, a1h, a2h, a3h, b0l, b1l);
            }
        }
    }
    __syncthreads();   // all MMAs done; smem A/H/W regions can be repurposed reads-first

    // ---- epilogue: added = acc + b2 + cust ----
    float addv[8][4];
#pragma unroll
    for (int jt = 0; jt < 8; jt++) {
        int colb = wc * 64 + jt * 8 + 2 * t4;
        int cp   = wc * 32 + jt * 4 + t4;
        float2 bb = *reinterpret_cast<const float2*>(b2 + colb);
        __nv_bfloat162 c0h = u2b(Ah[r0 * SA + cp]), c0l = u2b(Al[r0 * SA + cp]);
        __nv_bfloat162 c1h = u2b(Ah[r1 * SA + cp]), c1l = u2b(Al[r1 * SA + cp]);
        addv[jt][0] = acc[jt][0] + bb.x + __bfloat162float(c0h.x) + __bfloat162float(c0l.x);
        addv[jt][1] = acc[jt][1] + bb.y + __bfloat162float(c0h.y) + __bfloat162float(c0l.y);
        addv[jt][2] = acc[jt][2] + bb.x + __bfloat162float(c1h.x) + __bfloat162float(c1l.x);
        addv[jt][3] = acc[jt][3] + bb.y + __bfloat162float(c1h.y) + __bfloat162float(c1l.y);
    }
    __syncthreads();   // everyone finished reading Ah/Al; now overwrite as Ad tile
#pragma unroll
    for (int jt = 0; jt < 8; jt++) {
        int colb = wc * 64 + jt * 8 + 2 * t4;
        *reinterpret_cast<float2*>(Ad + r0 * 132 + colb) = make_float2(addv[jt][0], addv[jt][1]);
        *reinterpret_cast<float2*>(Ad + r1 * 132 + colb) = make_float2(addv[jt][2], addv[jt][3]);
        if (r0 < nrows)
            *reinterpret_cast<float2*>(g_added + (size_t)(b * PP + row0 + r0) * DD + colb) =
                make_float2(addv[jt][0], addv[jt][1]);
        if (r1 < nrows)
            *reinterpret_cast<float2*>(g_added + (size_t)(b * PP + row0 + r1) * DD + colb) =
                make_float2(addv[jt][2], addv[jt][3]);
    }
    __syncthreads();

    // ---- per-column sum / sumsq over valid rows ----
    {
        int col = tid & 127, half = tid >> 7;
        float s = 0.f, ss = 0.f;
        for (int r = half; r < nrows; r += 2) {
            float v = Ad[r * 132 + col];
            s += v; ss += v * v;
        }
        redc[half * 128 + col]       = s;
        redc[256 + half * 128 + col] = ss;
        __syncthreads();
        if (tid < 128) {
            float st  = redc[tid] + redc[128 + tid];
            float sst = redc[256 + tid] + redc[384 + tid];
            atomicAdd(&g_sum[b * DD + tid], st);
            atomicAdd(&g_sumsq[b * DD + tid], sst);
        }
    }
}

// ---------------- K4: stats -> (scale, shift) ----------------
__global__ void k_stat(const float* __restrict__ gamma, const float* __restrict__ beta) {
    int i = blockIdx.x * blockDim.x + threadIdx.x;
    if (i >= BB * DD) return;
    int d = i & 127;
    float mean = g_sum[i] * (1.f / PP);
    float var  = g_sumsq[i] * (1.f / PP) - mean * mean;
    float sc = gamma[d] * rsqrtf(var + EPSL);
    float sh = beta[d] - mean * sc;
    g_sum[i] = sc;
    g_sumsq[i] = sh;
}

// ---------------- K5: normalize + depot copy ----------------
__global__ void k_norm(const float* __restrict__ emb, float* __restrict__ out) {
    int i = blockIdx.x * blockDim.x + threadIdx.x;
    const int N4 = BB * 2001 * 32;
    if (i >= N4) return;
    int d4 = i & 31;
    int row = i >> 5;
    int b = row / 2001;
    int pr = row - b * 2001;
    float4 o;
    if (pr == 0) {
        o = reinterpret_cast<const float4*>(emb)[i];
    } else {
        int p = pr - 1;
        float4 a = *reinterpret_cast<const float4*>(g_added + (size_t)(b * PP + p) * DD + d4 * 4);
        float4 s4 = *reinterpret_cast<const float4*>(g_sum + b * DD + d4 * 4);
        float4 h4 = *reinterpret_cast<const float4*>(g_sumsq + b * DD + d4 * 4);
        o.x = a.x * s4.x + h4.x;
        o.y = a.y * s4.y + h4.y;
        o.z = a.z * s4.z + h4.z;
        o.w = a.w * s4.w + h4.w;
    }
    reinterpret_cast<float4*>(out)[i] = o;
}

// ---------------- launch ----------------
extern "C" void kernel_launch(void* const* d_in, const int* in_sizes, int n_in,
                              void* d_out, int out_size) {
    int ti = -1;
    for (int i = 0; i < n_in; i++)
        if (in_sizes[i] == BB * PP) { ti = i; break; }
    const int*   tidx  = (const int*)  d_in[ti];
    const float* emb   = (const float*)d_in[ti + 1];
    const float* W1    = (const float*)d_in[ti + 2];
    const float* b1    = (const float*)d_in[ti + 3];
    const float* W2    = (const float*)d_in[ti + 4];
    const float* b2    = (const float*)d_in[ti + 5];
    const float* gamma = (const float*)d_in[ti + 6];
    const float* beta  = (const float*)d_in[ti + 7];
    float* out = (float*)d_out;

    const int SMEM_TB   = (64 * 132 + 32 * 128) * 4;
    const int SMEM_MAIN = SMEM_U32 * 4;   // ~106.8 KB
    cudaFuncSetAttribute(k_tb,   cudaFuncAttributeMaxDynamicSharedMemorySize, SMEM_TB);
    cudaFuncSetAttribute(k_main, cudaFuncAttributeMaxDynamicSharedMemorySize, SMEM_MAIN);

    k_zero<<<(BB * TT * DD + 255) / 256, 256>>>();
    k_pack<<<(2 * DD * 64 + 255) / 256, 256>>>(W1, W2);
    k_seg<<<(BB * PP * 32 + 255) / 256, 256>>>(emb, tidx);
    k_tb<<<(BB * TT) / 64, 256, SMEM_TB>>>(W1, b1);
    k_main<<<dim3((PP + 63) / 64, BB), 256, SMEM_MAIN>>>(emb, tidx, b2);
    k_stat<<<(BB * DD + 255) / 256, 256>>>(gamma, beta);
    k_norm<<<(BB * 2001 * 32 + 255) / 256, 256>>>(emb, out);
}

// round 4
// speedup vs baseline: 2.9242x; 1.3641x over previous
#include <cuda_runtime.h>
#include <cuda_fp16.h>
#include <cstddef>

#define BB 64
#define PP 2000
#define DD 128
#define TT 200
#define EPSL 1e-5f

// ---------------- scratch ----------------
__device__ float g_tour [BB * TT * DD];
__device__ float g_tb   [BB * TT * DD];
__device__ float g_added[BB * PP * DD];
__device__ float g_sum  [BB * DD];
__device__ float g_sumsq[BB * DD];
// fp16x2 packed weights: [n][kp], kp in [0,64), pair = (W[2kp][n], W[2kp+1][n])
__device__ unsigned g_W1p[DD * 64];   // W1 rows [0,128)   (acts on cust)
__device__ unsigned g_Wbp[DD * 64];   // W1 rows [128,256) (acts on tour_emb)
__device__ unsigned g_W2p[DD * 64];

static __device__ __forceinline__ unsigned pack2(float v0, float v1) {
    __half2 h = __floats2half2_rn(v0, v1);
    return *reinterpret_cast<unsigned*>(&h);
}
static __device__ __forceinline__ void split_pack(float v0, float v1,
                                                  unsigned& hi, unsigned& lo) {
    __half2 h = __floats2half2_rn(v0, v1);
    float r0 = v0 - __half2float(__low2half(h));
    float r1 = v1 - __half2float(__high2half(h));
    hi = *reinterpret_cast<unsigned*>(&h);
    __half2 l = __floats2half2_rn(r0, r1);
    lo = *reinterpret_cast<unsigned*>(&l);
}
static __device__ __forceinline__ float2 unpack2(unsigned u) {
    __half2 h = *reinterpret_cast<__half2*>(&u);
    return make_float2(__half2float(__low2half(h)), __half2float(__high2half(h)));
}

static __device__ __forceinline__ void mma16816(float* c, unsigned a0, unsigned a1,
                                                unsigned a2, unsigned a3,
                                                unsigned b0, unsigned b1) {
    asm volatile(
        "mma.sync.aligned.m16n8k16.row.col.f32.f16.f16.f32 "
        "{%0,%1,%2,%3}, {%4,%5,%6,%7}, {%8,%9}, {%0,%1,%2,%3};"
        : "+f"(c[0]), "+f"(c[1]), "+f"(c[2]), "+f"(c[3])
        : "r"(a0), "r"(a1), "r"(a2), "r"(a3), "r"(b0), "r"(b1));
}

// ---------------- K0: zero ----------------
__global__ void k_zero() {
    int i = blockIdx.x * blockDim.x + threadIdx.x;
    if (i < BB * TT * DD) g_tour[i] = 0.f;
    if (i < BB * DD) { g_sum[i] = 0.f; g_sumsq[i] = 0.f; }
}

// ---------------- K pack: fp16-pack W1a, W1b, W2 ----------------
__global__ void k_pack(const float* __restrict__ W1, const float* __restrict__ W2) {
    int i = blockIdx.x * blockDim.x + threadIdx.x;   // 3 * 128 * 64
    if (i >= 3 * DD * 64) return;
    int m  = i >> 13;
    int n  = (i >> 6) & 127;
    int kp = i & 63;
    const float* W = (m == 0) ? W1 : (m == 1) ? (W1 + 128 * DD) : W2;
    unsigned p = pack2(W[(2 * kp) * DD + n], W[(2 * kp + 1) * DD + n]);
    if (m == 0)      g_W1p[n * 64 + kp] = p;
    else if (m == 1) g_Wbp[n * 64 + kp] = p;
    else             g_W2p[n * 64 + kp] = p;
}

// ---------------- K1: segment sum (vector global atomics) ----------------
__global__ void k_seg(const float* __restrict__ emb, const int* __restrict__ tidx) {
    int i = blockIdx.x * blockDim.x + threadIdx.x;
    int d4 = i & 31;
    int r  = i >> 5;
    if (r >= BB * PP) return;
    int b = r / PP, p = r - b * PP;
    const float4 v = *reinterpret_cast<const float4*>(emb + (size_t)(b * 2001 + 1 + p) * DD + d4 * 4);
    int t = tidx[r];
    float4* dst = reinterpret_cast<float4*>(g_tour + (size_t)(b * TT + t) * DD + d4 * 4);
    atomicAdd(dst, v);
}

// ---------------- K2: tb = tour_emb @ W1b + b1 (fp16 MMA) ----------------
// smem u32: A[64*68], W[128*68]
#define TB_OFF_W (64 * 68)
#define TB_SMEM_U32 (TB_OFF_W + 128 * 68)
__global__ void __launch_bounds__(256, 2)
k_tb(const float* __restrict__ b1) {
    extern __shared__ unsigned su[];
    unsigned* As = su;
    unsigned* Ws = su + TB_OFF_W;
    int tid = threadIdx.x;
    int lane = tid & 31, wid = tid >> 5;
    int g = lane >> 2, t4 = lane & 3;
    int wr = wid & 3, wc = wid >> 2;
    int row0 = blockIdx.x * 64;

    for (int i = tid; i < 64 * 32; i += 256) {          // pack A tile
        int r = i >> 5, c4 = i & 31;
        float4 v = *reinterpret_cast<const float4*>(g_tour + (size_t)(row0 + r) * DD + c4 * 4);
        As[r * 68 + 2 * c4]     = pack2(v.x, v.y);
        As[r * 68 + 2 * c4 + 1] = pack2(v.z, v.w);
    }
    for (int i = tid; i < 2048; i += 256) {             // full W1b
        int n = i >> 4, k4 = (i & 15) * 4;
        *reinterpret_cast<uint4*>(Ws + n * 68 + k4) =
            *reinterpret_cast<const uint4*>(g_Wbp + n * 64 + k4);
    }
    __syncthreads();

    float acc[8][4];
#pragma unroll
    for (int j = 0; j < 8; j++)
#pragma unroll
        for (int i = 0; i < 4; i++) acc[j][i] = 0.f;
    int r0 = wr * 16 + g, r1 = r0 + 8;

#pragma unroll
    for (int s = 0; s < 8; s++) {
        unsigned a0 = As[r0 * 68 + s * 8 + t4];
        unsigned a1 = As[r1 * 68 + s * 8 + t4];
        unsigned a2 = As[r0 * 68 + s * 8 + t4 + 4];
        unsigned a3 = As[r1 * 68 + s * 8 + t4 + 4];
#pragma unroll
        for (int jt = 0; jt < 8; jt++) {
            int n = wc * 64 + jt * 8 + g;
            mma16816(acc[jt], a0, a1, a2, a3,
                     Ws[n * 68 + s * 8 + t4], Ws[n * 68 + s * 8 + t4 + 4]);
        }
    }

#pragma unroll
    for (int jt = 0; jt < 8; jt++) {
        int colb = wc * 64 + jt * 8 + 2 * t4;
        float2 bb = *reinterpret_cast<const float2*>(b1 + colb);
        *reinterpret_cast<float2*>(g_tb + (size_t)(row0 + r0) * DD + colb) =
            make_float2(acc[jt][0] + bb.x, acc[jt][1] + bb.y);
        *reinterpret_cast<float2*>(g_tb + (size_t)(row0 + r1) * DD + colb) =
            make_float2(acc[jt][2] + bb.x, acc[jt][3] + bb.y);
    }
}

// ---------------- K3: fused MLP, fp16 MMA ----------------
// smem u32: Ah[64*68], Al[64*68] (epilogue-only residual), H[64*68], W[128*68], ts[64]
// After MMAs: Ad f32[64][132] aliases Ah..Al; redc f32[512] aliases W.
#define OFF_AL (64 * 68)
#define OFF_H  (2 * 64 * 68)
#define OFF_W  (3 * 64 * 68)
#define OFF_TS (3 * 64 * 68 + 128 * 68)
#define SMEM_U32 (OFF_TS + 64)

__global__ void __launch_bounds__(256, 2)
k_main(const float* __restrict__ emb, const int* __restrict__ tidx,
       const float* __restrict__ b2) {
    extern __shared__ unsigned su[];
    unsigned* Ah = su;
    unsigned* Al = su + OFF_AL;
    unsigned* Hs = su + OFF_H;
    unsigned* Ws = su + OFF_W;
    int* ts = (int*)(su + OFF_TS);
    float* Ad   = (float*)su;             // [64][132] after epilogue read
    float* redc = (float*)(su + OFF_W);   // [512]

    int tid = threadIdx.x;
    int lane = tid & 31, wid = tid >> 5;
    int g = lane >> 2, t4 = lane & 3;
    int wr = wid & 3, wc = wid >> 2;
    int b = blockIdx.y;
    int row0 = blockIdx.x * 64;
    int nrows = PP - row0; if (nrows > 64) nrows = 64;

    // ---- pack A tile (hi for mma, lo for exact residual) + W1 + ts ----
    for (int i = tid; i < 64 * 32; i += 256) {
        int r = i >> 5, c4 = i & 31;
        float4 v = make_float4(0.f, 0.f, 0.f, 0.f);
        if (r < nrows)
            v = *reinterpret_cast<const float4*>(emb + (size_t)(b * 2001 + 1 + row0 + r) * DD + c4 * 4);
        unsigned h0, l0, h1, l1;
        split_pack(v.x, v.y, h0, l0);
        split_pack(v.z, v.w, h1, l1);
        Ah[r * 68 + 2 * c4]     = h0;  Al[r * 68 + 2 * c4]     = l0;
        Ah[r * 68 + 2 * c4 + 1] = h1;  Al[r * 68 + 2 * c4 + 1] = l1;
    }
    for (int i = tid; i < 2048; i += 256) {
        int n = i >> 4, k4 = (i & 15) * 4;
        *reinterpret_cast<uint4*>(Ws + n * 68 + k4) =
            *reinterpret_cast<const uint4*>(g_W1p + n * 64 + k4);
    }
    if (tid < 64) {
        int t = 0;
        if (tid < nrows) t = tidx[b * PP + row0 + tid];
        ts[tid] = t;
    }
    __syncthreads();

    float acc[8][4];
#pragma unroll
    for (int j = 0; j < 8; j++)
#pragma unroll
        for (int i = 0; i < 4; i++) acc[j][i] = 0.f;
    int r0 = wr * 16 + g, r1 = r0 + 8;

    // ---- phase 1: acc = A @ W1a ----
#pragma unroll
    for (int s = 0; s < 8; s++) {
        unsigned a0 = Ah[r0 * 68 + s * 8 + t4];
        unsigned a1 = Ah[r1 * 68 + s * 8 + t4];
        unsigned a2 = Ah[r0 * 68 + s * 8 + t4 + 4];
        unsigned a3 = Ah[r1 * 68 + s * 8 + t4 + 4];
#pragma unroll
        for (int jt = 0; jt < 8; jt++) {
            int n = wc * 64 + jt * 8 + g;
            mma16816(acc[jt], a0, a1, a2, a3,
                     Ws[n * 68 + s * 8 + t4], Ws[n * 68 + s * 8 + t4 + 4]);
        }
    }

    // ---- tb gather + relu -> H (fp16) ----
    {
        const float* tb0p = g_tb + (size_t)(b * TT + ts[r0]) * DD;
        const float* tb1p = g_tb + (size_t)(b * TT + ts[r1]) * DD;
#pragma unroll
        for (int jt = 0; jt < 8; jt++) {
            int colb = wc * 64 + jt * 8 + 2 * t4;
            int cp   = wc * 32 + jt * 4 + t4;
            float2 tb0 = *reinterpret_cast<const float2*>(tb0p + colb);
            float2 tb1 = *reinterpret_cast<const float2*>(tb1p + colb);
            Hs[r0 * 68 + cp] = pack2(fmaxf(acc[jt][0] + tb0.x, 0.f),
                                     fmaxf(acc[jt][1] + tb0.y, 0.f));
            Hs[r1 * 68 + cp] = pack2(fmaxf(acc[jt][2] + tb1.x, 0.f),
                                     fmaxf(acc[jt][3] + tb1.y, 0.f));
#pragma unroll
            for (int i = 0; i < 4; i++) acc[jt][i] = 0.f;
        }
    }
    __syncthreads();            // H complete; W1 reads done

    // ---- load W2, phase 2: acc = H @ W2 ----
    for (int i = tid; i < 2048; i += 256) {
        int n = i >> 4, k4 = (i & 15) * 4;
        *reinterpret_cast<uint4*>(Ws + n * 68 + k4) =
            *reinterpret_cast<const uint4*>(g_W2p + n * 64 + k4);
    }
    __syncthreads();
#pragma unroll
    for (int s = 0; s < 8; s++) {
        unsigned a0 = Hs[r0 * 68 + s * 8 + t4];
        unsigned a1 = Hs[r1 * 68 + s * 8 + t4];
        unsigned a2 = Hs[r0 * 68 + s * 8 + t4 + 4];
        unsigned a3 = Hs[r1 * 68 + s * 8 + t4 + 4];
#pragma unroll
        for (int jt = 0; jt < 8; jt++) {
            int n = wc * 64 + jt * 8 + g;
            mma16816(acc[jt], a0, a1, a2, a3,
                     Ws[n * 68 + s * 8 + t4], Ws[n * 68 + s * 8 + t4 + 4]);
        }
    }
    __syncthreads();

    // ---- epilogue: added = acc + b2 + cust (exact via hi+lo) ----
    float addv[8][4];
#pragma unroll
    for (int jt = 0; jt < 8; jt++) {
        int colb = wc * 64 + jt * 8 + 2 * t4;
        int cp   = wc * 32 + jt * 4 + t4;
        float2 bb = *reinterpret_cast<const float2*>(b2 + colb);
        float2 c0h = unpack2(Ah[r0 * 68 + cp]), c0l = unpack2(Al[r0 * 68 + cp]);
        float2 c1h = unpack2(Ah[r1 * 68 + cp]), c1l = unpack2(Al[r1 * 68 + cp]);
        addv[jt][0] = acc[jt][0] + bb.x + c0h.x + c0l.x;
        addv[jt][1] = acc[jt][1] + bb.y + c0h.y + c0l.y;
        addv[jt][2] = acc[jt][2] + bb.x + c1h.x + c1l.x;
        addv[jt][3] = acc[jt][3] + bb.y + c1h.y + c1l.y;
    }
    __syncthreads();            // done reading Ah/Al; reuse as Ad
#pragma unroll
    for (int jt = 0; jt < 8; jt++) {
        int colb = wc * 64 + jt * 8 + 2 * t4;
        *reinterpret_cast<float2*>(Ad + r0 * 132 + colb) = make_float2(addv[jt][0], addv[jt][1]);
        *reinterpret_cast<float2*>(Ad + r1 * 132 + colb) = make_float2(addv[jt][2], addv[jt][3]);
        if (r0 < nrows)
            *reinterpret_cast<float2*>(g_added + (size_t)(b * PP + row0 + r0) * DD + colb) =
                make_float2(addv[jt][0], addv[jt][1]);
        if (r1 < nrows)
            *reinterpret_cast<float2*>(g_added + (size_t)(b * PP + row0 + r1) * DD + colb) =
                make_float2(addv[jt][2], addv[jt][3]);
    }
    __syncthreads();

    // ---- per-column sum / sumsq over valid rows ----
    {
        int col = tid & 127, half = tid >> 7;
        float s = 0.f, ss = 0.f;
        for (int r = half; r < nrows; r += 2) {
            float v = Ad[r * 132 + col];
            s += v; ss += v * v;
        }
        redc[half * 128 + col]       = s;
        redc[256 + half * 128 + col] = ss;
        __syncthreads();
        if (tid < 128) {
            float st  = redc[tid] + redc[128 + tid];
            float sst = redc[256 + tid] + redc[384 + tid];
            atomicAdd(&g_sum[b * DD + tid], st);
            atomicAdd(&g_sumsq[b * DD + tid], sst);
        }
    }
}

// ---------------- K4: stats -> (scale, shift) ----------------
__global__ void k_stat(const float* __restrict__ gamma, const float* __restrict__ beta) {
    int i = blockIdx.x * blockDim.x + threadIdx.x;
    if (i >= BB * DD) return;
    int d = i & 127;
    float mean = g_sum[i] * (1.f / PP);
    float var  = g_sumsq[i] * (1.f / PP) - mean * mean;
    float sc = gamma[d] * rsqrtf(var + EPSL);
    float sh = beta[d] - mean * sc;
    g_sum[i] = sc;
    g_sumsq[i] = sh;
}

// ---------------- K5: normalize + depot copy ----------------
__global__ void k_norm(const float* __restrict__ emb, float* __restrict__ out) {
    int i = blockIdx.x * blockDim.x + threadIdx.x;
    const int N4 = BB * 2001 * 32;
    if (i >= N4) return;
    int d4 = i & 31;
    int row = i >> 5;
    int b = row / 2001;
    int pr = row - b * 2001;
    float4 o;
    if (pr == 0) {
        o = reinterpret_cast<const float4*>(emb)[i];
    } else {
        int p = pr - 1;
        float4 a = *reinterpret_cast<const float4*>(g_added + (size_t)(b * PP + p) * DD + d4 * 4);
        float4 s4 = *reinterpret_cast<const float4*>(g_sum + b * DD + d4 * 4);
        float4 h4 = *reinterpret_cast<const float4*>(g_sumsq + b * DD + d4 * 4);
        o.x = a.x * s4.x + h4.x;
        o.y = a.y * s4.y + h4.y;
        o.z = a.z * s4.z + h4.z;
        o.w = a.w * s4.w + h4.w;
    }
    reinterpret_cast<float4*>(out)[i] = o;
}

// ---------------- launch ----------------
extern "C" void kernel_launch(void* const* d_in, const int* in_sizes, int n_in,
                              void* d_out, int out_size) {
    int ti = -1;
    for (int i = 0; i < n_in; i++)
        if (in_sizes[i] == BB * PP) { ti = i; break; }
    const int*   tidx  = (const int*)  d_in[ti];
    const float* emb   = (const float*)d_in[ti + 1];
    const float* W1    = (const float*)d_in[ti + 2];
    const float* b1    = (const float*)d_in[ti + 3];
    const float* W2    = (const float*)d_in[ti + 4];
    const float* b2    = (const float*)d_in[ti + 5];
    const float* gamma = (const float*)d_in[ti + 6];
    const float* beta  = (const float*)d_in[ti + 7];
    float* out = (float*)d_out;

    const int SMEM_TB   = TB_SMEM_U32 * 4;   // ~52 KB
    const int SMEM_MAIN = SMEM_U32 * 4;      // ~87 KB
    cudaFuncSetAttribute(k_tb,   cudaFuncAttributeMaxDynamicSharedMemorySize, SMEM_TB);
    cudaFuncSetAttribute(k_main, cudaFuncAttributeMaxDynamicSharedMemorySize, SMEM_MAIN);

    k_zero<<<(BB * TT * DD + 255) / 256, 256>>>();
    k_pack<<<(3 * DD * 64 + 255) / 256, 256>>>(W1, W2);
    k_seg<<<(BB * PP * 32 + 255) / 256, 256>>>(emb, tidx);
    k_tb<<<(BB * TT) / 64, 256, SMEM_TB>>>(b1);
    k_main<<<dim3((PP + 63) / 64, BB), 256, SMEM_MAIN>>>(emb, tidx, b2);
    k_stat<<<(BB * DD + 255) / 256, 256>>>(gamma, beta);
    k_norm<<<(BB * 2001 * 32 + 255) / 256, 256>>>(emb, out);
}

// round 5
// speedup vs baseline: 3.3664x; 1.1512x over previous
#include <cuda_runtime.h>
#include <cuda_fp16.h>
#include <cstddef>

#define BB 64
#define PP 2000
#define DD 128
#define TT 200
#define EPSL 1e-5f

// ---------------- scratch ----------------
__device__ float g_tour [BB * TT * DD];
__device__ float g_tb   [BB * TT * DD];
__device__ float g_added[BB * PP * DD];
__device__ float g_sum  [BB * DD];
__device__ float g_sumsq[BB * DD];
// fp16x2 packed weights: [n][kp], kp in [0,64), pair = (W[2kp][n], W[2kp+1][n])
__device__ unsigned g_W1p[DD * 64];   // W1 rows [0,128)
__device__ unsigned g_Wbp[DD * 64];   // W1 rows [128,256)
__device__ unsigned g_W2p[DD * 64];

static __device__ __forceinline__ unsigned pack2(float v0, float v1) {
    __half2 h = __floats2half2_rn(v0, v1);
    return *reinterpret_cast<unsigned*>(&h);
}

static __device__ __forceinline__ void mma16816(float* c, unsigned a0, unsigned a1,
                                                unsigned a2, unsigned a3,
                                                unsigned b0, unsigned b1) {
    asm volatile(
        "mma.sync.aligned.m16n8k16.row.col.f32.f16.f16.f32 "
        "{%0,%1,%2,%3}, {%4,%5,%6,%7}, {%8,%9}, {%0,%1,%2,%3};"
        : "+f"(c[0]), "+f"(c[1]), "+f"(c[2]), "+f"(c[3])
        : "r"(a0), "r"(a1), "r"(a2), "r"(a3), "r"(b0), "r"(b1));
}

// ---------------- K0: zero + pack weights (merged) ----------------
__global__ void k_init(const float* __restrict__ W1, const float* __restrict__ W2) {
    int i = blockIdx.x * blockDim.x + threadIdx.x;
    if (i < BB * TT * DD) g_tour[i] = 0.f;
    if (i < BB * DD) { g_sum[i] = 0.f; g_sumsq[i] = 0.f; }
    if (i < 3 * DD * 64) {
        int m  = i >> 13;
        int n  = (i >> 6) & 127;
        int kp = i & 63;
        const float* W = (m == 0) ? W1 : (m == 1) ? (W1 + 128 * DD) : W2;
        unsigned p = pack2(W[(2 * kp) * DD + n], W[(2 * kp + 1) * DD + n]);
        if (m == 0)      g_W1p[n * 64 + kp] = p;
        else if (m == 1) g_Wbp[n * 64 + kp] = p;
        else             g_W2p[n * 64 + kp] = p;
    }
}

// ---------------- K1: segment sum (vector global atomics) ----------------
__global__ void k_seg(const float* __restrict__ emb, const int* __restrict__ tidx) {
    int i = blockIdx.x * blockDim.x + threadIdx.x;
    int d4 = i & 31;
    int r  = i >> 5;
    if (r >= BB * PP) return;
    int b = r / PP, p = r - b * PP;
    const float4 v = *reinterpret_cast<const float4*>(emb + (size_t)(b * 2001 + 1 + p) * DD + d4 * 4);
    int t = tidx[r];
    float4* dst = reinterpret_cast<float4*>(g_tour + (size_t)(b * TT + t) * DD + d4 * 4);
    atomicAdd(dst, v);
}

// ---------------- K2: tb = tour_emb @ W1b + b1 (fp16 MMA, 32-row tiles) ----------------
// block 128 threads (4 warps: 2 row-groups x 2 col-halves), grid 400
#define TB_OFF_W (32 * 68)
#define TB_SMEM_U32 (TB_OFF_W + 128 * 68)
__global__ void __launch_bounds__(128, 5)
k_tb(const float* __restrict__ b1) {
    extern __shared__ unsigned su[];
    unsigned* As = su;
    unsigned* Ws = su + TB_OFF_W;
    int tid = threadIdx.x;
    int lane = tid & 31, wid = tid >> 5;
    int g = lane >> 2, t4 = lane & 3;
    int wr = wid & 1, wc = wid >> 1;
    int row0 = blockIdx.x * 32;

    for (int i = tid; i < 32 * 32; i += 128) {          // pack A tile (32 x 128)
        int r = i >> 5, c4 = i & 31;
        float4 v = *reinterpret_cast<const float4*>(g_tour + (size_t)(row0 + r) * DD + c4 * 4);
        As[r * 68 + 2 * c4]     = pack2(v.x, v.y);
        As[r * 68 + 2 * c4 + 1] = pack2(v.z, v.w);
    }
    for (int i = tid; i < 2048; i += 128) {             // full W1b
        int n = i >> 4, k4 = (i & 15) * 4;
        *reinterpret_cast<uint4*>(Ws + n * 68 + k4) =
            *reinterpret_cast<const uint4*>(g_Wbp + n * 64 + k4);
    }
    __syncthreads();

    float acc[8][4];
#pragma unroll
    for (int j = 0; j < 8; j++)
#pragma unroll
        for (int i = 0; i < 4; i++) acc[j][i] = 0.f;
    int r0 = wr * 16 + g, r1 = r0 + 8;

#pragma unroll
    for (int s = 0; s < 8; s++) {
        unsigned a0 = As[r0 * 68 + s * 8 + t4];
        unsigned a1 = As[r1 * 68 + s * 8 + t4];
        unsigned a2 = As[r0 * 68 + s * 8 + t4 + 4];
        unsigned a3 = As[r1 * 68 + s * 8 + t4 + 4];
#pragma unroll
        for (int jt = 0; jt < 8; jt++) {
            int n = wc * 64 + jt * 8 + g;
            mma16816(acc[jt], a0, a1, a2, a3,
                     Ws[n * 68 + s * 8 + t4], Ws[n * 68 + s * 8 + t4 + 4]);
        }
    }

#pragma unroll
    for (int jt = 0; jt < 8; jt++) {
        int colb = wc * 64 + jt * 8 + 2 * t4;
        float2 bb = *reinterpret_cast<const float2*>(b1 + colb);
        *reinterpret_cast<float2*>(g_tb + (size_t)(row0 + r0) * DD + colb) =
            make_float2(acc[jt][0] + bb.x, acc[jt][1] + bb.y);
        *reinterpret_cast<float2*>(g_tb + (size_t)(row0 + r1) * DD + colb) =
            make_float2(acc[jt][2] + bb.x, acc[jt][3] + bb.y);
    }
}

// ---------------- K3: fused MLP, fp16 MMA ----------------
// smem u32: Ah[64*68], H[64*68], W[128*68], ts[64]   (~70 KB -> 3 CTAs/SM)
// After phase2: Ad f32[64][132] aliases Ah+H; redc f32[2048] aliases W.
#define OFF_H  (64 * 68)
#define OFF_W  (2 * 64 * 68)
#define OFF_TS (2 * 64 * 68 + 128 * 68)
#define SMEM_U32 (OFF_TS + 64)

__global__ void __launch_bounds__(256, 3)
k_main(const float* __restrict__ emb, const int* __restrict__ tidx,
       const float* __restrict__ b2) {
    extern __shared__ unsigned su[];
    unsigned* Ah = su;
    unsigned* Hs = su + OFF_H;
    unsigned* Ws = su + OFF_W;
    int* ts = (int*)(su + OFF_TS);
    float* Ad   = (float*)su;             // [64][132] after phase2
    float* redc = (float*)(su + OFF_W);   // [2048]

    int tid = threadIdx.x;
    int lane = tid & 31, wid = tid >> 5;
    int g = lane >> 2, t4 = lane & 3;
    int wr = wid & 3, wc = wid >> 2;
    int b = blockIdx.y;
    int row0 = blockIdx.x * 64;
    int nrows = PP - row0; if (nrows > 64) nrows = 64;

    // ---- pack A tile (fp16) + load W1 + tour ids ----
    for (int i = tid; i < 64 * 32; i += 256) {
        int r = i >> 5, c4 = i & 31;
        float4 v = make_float4(0.f, 0.f, 0.f, 0.f);
        if (r < nrows)
            v = *reinterpret_cast<const float4*>(emb + (size_t)(b * 2001 + 1 + row0 + r) * DD + c4 * 4);
        Ah[r * 68 + 2 * c4]     = pack2(v.x, v.y);
        Ah[r * 68 + 2 * c4 + 1] = pack2(v.z, v.w);
    }
    for (int i = tid; i < 2048; i += 256) {
        int n = i >> 4, k4 = (i & 15) * 4;
        *reinterpret_cast<uint4*>(Ws + n * 68 + k4) =
            *reinterpret_cast<const uint4*>(g_W1p + n * 64 + k4);
    }
    if (tid < 64) {
        int t = 0;
        if (tid < nrows) t = tidx[b * PP + row0 + tid];
        ts[tid] = t;
    }
    __syncthreads();

    float acc[8][4];
#pragma unroll
    for (int j = 0; j < 8; j++)
#pragma unroll
        for (int i = 0; i < 4; i++) acc[j][i] = 0.f;
    int r0 = wr * 16 + g, r1 = r0 + 8;

    // ---- phase 1: acc = A @ W1a ----
#pragma unroll
    for (int s = 0; s < 8; s++) {
        unsigned a0 = Ah[r0 * 68 + s * 8 + t4];
        unsigned a1 = Ah[r1 * 68 + s * 8 + t4];
        unsigned a2 = Ah[r0 * 68 + s * 8 + t4 + 4];
        unsigned a3 = Ah[r1 * 68 + s * 8 + t4 + 4];
#pragma unroll
        for (int jt = 0; jt < 8; jt++) {
            int n = wc * 64 + jt * 8 + g;
            mma16816(acc[jt], a0, a1, a2, a3,
                     Ws[n * 68 + s * 8 + t4], Ws[n * 68 + s * 8 + t4 + 4]);
        }
    }

    // ---- tb gather + relu -> H (fp16) ----
    {
        const float* tb0p = g_tb + (size_t)(b * TT + ts[r0]) * DD;
        const float* tb1p = g_tb + (size_t)(b * TT + ts[r1]) * DD;
#pragma unroll
        for (int jt = 0; jt < 8; jt++) {
            int colb = wc * 64 + jt * 8 + 2 * t4;
            int cp   = wc * 32 + jt * 4 + t4;
            float2 tb0 = *reinterpret_cast<const float2*>(tb0p + colb);
            float2 tb1 = *reinterpret_cast<const float2*>(tb1p + colb);
            Hs[r0 * 68 + cp] = pack2(fmaxf(acc[jt][0] + tb0.x, 0.f),
                                     fmaxf(acc[jt][1] + tb0.y, 0.f));
            Hs[r1 * 68 + cp] = pack2(fmaxf(acc[jt][2] + tb1.x, 0.f),
                                     fmaxf(acc[jt][3] + tb1.y, 0.f));
#pragma unroll
            for (int i = 0; i < 4; i++) acc[jt][i] = 0.f;
        }
    }
    __syncthreads();            // H complete; W1 reads done

    // ---- load W2, phase 2: acc = H @ W2 ----
    for (int i = tid; i < 2048; i += 256) {
        int n = i >> 4, k4 = (i & 15) * 4;
        *reinterpret_cast<uint4*>(Ws + n * 68 + k4) =
            *reinterpret_cast<const uint4*>(g_W2p + n * 64 + k4);
    }
    __syncthreads();
#pragma unroll
    for (int s = 0; s < 8; s++) {
        unsigned a0 = Hs[r0 * 68 + s * 8 + t4];
        unsigned a1 = Hs[r1 * 68 + s * 8 + t4];
        unsigned a2 = Hs[r0 * 68 + s * 8 + t4 + 4];
        unsigned a3 = Hs[r1 * 68 + s * 8 + t4 + 4];
#pragma unroll
        for (int jt = 0; jt < 8; jt++) {
            int n = wc * 64 + jt * 8 + g;
            mma16816(acc[jt], a0, a1, a2, a3,
                     Ws[n * 68 + s * 8 + t4], Ws[n * 68 + s * 8 + t4 + 4]);
        }
    }
    __syncthreads();            // MMA smem reads done; Ah/Hs/Ws reusable

    // ---- epilogue: added = acc + b2 + cust (exact f32 re-read) -> Ad ----
    {
        int rr0 = row0 + r0; if (rr0 > PP - 1) rr0 = PP - 1;
        int rr1 = row0 + r1; if (rr1 > PP - 1) rr1 = PP - 1;
        const float* e0 = emb + (size_t)(b * 2001 + 1 + rr0) * DD;
        const float* e1 = emb + (size_t)(b * 2001 + 1 + rr1) * DD;
#pragma unroll
        for (int jt = 0; jt < 8; jt++) {
            int colb = wc * 64 + jt * 8 + 2 * t4;
            float2 bb = *reinterpret_cast<const float2*>(b2 + colb);
            float2 c0 = *reinterpret_cast<const float2*>(e0 + colb);
            float2 c1 = *reinterpret_cast<const float2*>(e1 + colb);
            *reinterpret_cast<float2*>(Ad + r0 * 132 + colb) =
                make_float2(acc[jt][0] + bb.x + c0.x, acc[jt][1] + bb.y + c0.y);
            *reinterpret_cast<float2*>(Ad + r1 * 132 + colb) =
                make_float2(acc[jt][2] + bb.x + c1.x, acc[jt][3] + bb.y + c1.y);
        }
    }
    __syncthreads();

    // ---- fused coalesced store + column sum/sumsq ----
    {
        int c4 = tid & 31;        // 16B chunk within row
        int rg = tid >> 5;        // row group (8 rows each)
        float s0 = 0.f, s1 = 0.f, s2 = 0.f, s3 = 0.f;
        float q0 = 0.f, q1 = 0.f, q2 = 0.f, q3 = 0.f;
#pragma unroll
        for (int m = 0; m < 8; m++) {
            int r = rg + m * 8;
            if (r < nrows) {
                float4 v = *reinterpret_cast<const float4*>(Ad + r * 132 + c4 * 4);
                *reinterpret_cast<float4*>(g_added + (size_t)(b * PP + row0 + r) * DD + c4 * 4) = v;
                s0 += v.x; s1 += v.y; s2 += v.z; s3 += v.w;
                q0 += v.x * v.x; q1 += v.y * v.y; q2 += v.z * v.z; q3 += v.w * v.w;
            }
        }
        __syncthreads();          // Ad reads done; redc (aliases Ws) writable
        float* rs = redc + rg * 128 + c4 * 4;
        rs[0] = s0; rs[1] = s1; rs[2] = s2; rs[3] = s3;
        float* rq = redc + 1024 + rg * 128 + c4 * 4;
        rq[0] = q0; rq[1] = q1; rq[2] = q2; rq[3] = q3;
        __syncthreads();
        if (tid < 128) {
            float s = 0.f;
#pragma unroll
            for (int m = 0; m < 8; m++) s += redc[m * 128 + tid];
            atomicAdd(&g_sum[b * DD + tid], s);
        } else {
            int col = tid - 128;
            float q = 0.f;
#pragma unroll
            for (int m = 0; m < 8; m++) q += redc[1024 + m * 128 + col];
            atomicAdd(&g_sumsq[b * DD + col], q);
        }
    }
}

// ---------------- K4: stats -> (scale, shift) ----------------
__global__ void k_stat(const float* __restrict__ gamma, const float* __restrict__ beta) {
    int i = blockIdx.x * blockDim.x + threadIdx.x;
    if (i >= BB * DD) return;
    int d = i & 127;
    float mean = g_sum[i] * (1.f / PP);
    float var  = g_sumsq[i] * (1.f / PP) - mean * mean;
    float sc = gamma[d] * rsqrtf(var + EPSL);
    float sh = beta[d] - mean * sc;
    g_sum[i] = sc;
    g_sumsq[i] = sh;
}

// ---------------- K5: normalize + depot copy ----------------
__global__ void k_norm(const float* __restrict__ emb, float* __restrict__ out) {
    int i = blockIdx.x * blockDim.x + threadIdx.x;
    const int N4 = BB * 2001 * 32;
    if (i >= N4) return;
    int d4 = i & 31;
    int row = i >> 5;
    int b = row / 2001;
    int pr = row - b * 2001;
    float4 o;
    if (pr == 0) {
        o = reinterpret_cast<const float4*>(emb)[i];
    } else {
        int p = pr - 1;
        float4 a = *reinterpret_cast<const float4*>(g_added + (size_t)(b * PP + p) * DD + d4 * 4);
        float4 s4 = *reinterpret_cast<const float4*>(g_sum + b * DD + d4 * 4);
        float4 h4 = *reinterpret_cast<const float4*>(g_sumsq + b * DD + d4 * 4);
        o.x = a.x * s4.x + h4.x;
        o.y = a.y * s4.y + h4.y;
        o.z = a.z * s4.z + h4.z;
        o.w = a.w * s4.w + h4.w;
    }
    reinterpret_cast<float4*>(out)[i] = o;
}

// ---------------- launch ----------------
extern "C" void kernel_launch(void* const* d_in, const int* in_sizes, int n_in,
                              void* d_out, int out_size) {
    int ti = -1;
    for (int i = 0; i < n_in; i++)
        if (in_sizes[i] == BB * PP) { ti = i; break; }
    const int*   tidx  = (const int*)  d_in[ti];
    const float* emb   = (const float*)d_in[ti + 1];
    const float* W1    = (const float*)d_in[ti + 2];
    const float* b1    = (const float*)d_in[ti + 3];
    const float* W2    = (const float*)d_in[ti + 4];
    const float* b2    = (const float*)d_in[ti + 5];
    const float* gamma = (const float*)d_in[ti + 6];
    const float* beta  = (const float*)d_in[ti + 7];
    float* out = (float*)d_out;

    const int SMEM_TB   = TB_SMEM_U32 * 4;   // ~43.5 KB
    const int SMEM_MAIN = SMEM_U32 * 4;      // ~70 KB
    cudaFuncSetAttribute(k_tb,   cudaFuncAttributeMaxDynamicSharedMemorySize, SMEM_TB);
    cudaFuncSetAttribute(k_main, cudaFuncAttributeMaxDynamicSharedMemorySize, SMEM_MAIN);

    k_init<<<(BB * TT * DD + 255) / 256, 256>>>(W1, W2);
    k_seg<<<(BB * PP * 32 + 255) / 256, 256>>>(emb, tidx);
    k_tb<<<(BB * TT) / 32, 128, SMEM_TB>>>(b1);
    k_main<<<dim3((PP + 63) / 64, BB), 256, SMEM_MAIN>>>(emb, tidx, b2);
    k_stat<<<(BB * DD + 255) / 256, 256>>>(gamma, beta);
    k_norm<<<(BB * 2001 * 32 + 255) / 256, 256>>>(emb, out);
}